// round 16
// baseline (speedup 1.0000x reference)
#include <cuda_runtime.h>
#include <cuda_bf16.h>
#include <math.h>

#define NSAMP 64
#define TLEN  512
#define DDIM  16
#define NDIAG 1023
#define BIGL  1.0e10f
#define LOG2E 1.4426950408889634f
#define LN2   0.6931471805599453f
#define NPHASE 131   // 4 warps, lag 8: warp 3 reaches diag 1022 at phase 130

// log2(2+t) on t in (-1,1] — degree-6 poly (Chebyshev of ln(1+t/2), /ln2, +1)
#define PB0 1.00003728f
#define PB1 0.7216216f
#define PB2 (-0.1806254f)
#define PB3 0.0580670f
#define PB4 (-0.0212055f)
#define PB5 0.0127541f
#define PB6 (-0.0056955f)

__device__ float g_res[NSAMP];

typedef unsigned long long ull;

__device__ __forceinline__ float ex2f(float x){ float y; asm("ex2.approx.ftz.f32 %0, %1;" : "=f"(y) : "f"(x)); return y; }
__device__ __forceinline__ ull mul2(ull a, ull b){ ull d; asm("mul.rn.f32x2 %0, %1, %2;" : "=l"(d) : "l"(a), "l"(b)); return d; }
__device__ __forceinline__ ull add2(ull a, ull b){ ull d; asm("add.rn.f32x2 %0, %1, %2;" : "=l"(d) : "l"(a), "l"(b)); return d; }
__device__ __forceinline__ ull fma2(ull a, ull b, ull c){ ull d; asm("fma.rn.f32x2 %0, %1, %2, %3;" : "=l"(d) : "l"(a), "l"(b), "l"(c)); return d; }
#define UNPK(LO, HI, P) asm("mov.b64 {%0, %1}, %2;" : "=f"(LO), "=f"(HI) : "l"(P))
#define PK(P, LO, HI)   asm("mov.b64 %0, {%1, %2};" : "=l"(P) : "f"(LO), "f"(HI))

// Z permutation (R11-proven): row z -> slot (z>>2) + 128*(z&3); lanes are
// 4 z-rows apart -> consecutive slots; 18-float pitch => conflict-free.
#define ZSLOT(z) (((z) >> 2) + 128 * ((z) & 3))

// ---------------------------------------------------------------------------
// FUSED soft-DTW (R15 base + poly-log2 softmin: MUFU 12 -> 8 per SMSP-diag).
// 1 CTA/sample, 128 threads = 4 warps (1/SMSP), 4 cells/thread.
// Staircase lag 8, rings[5][32]. D computed on the fly one diagonal ahead.
// No band mask (BIGL is an fp32 fixed point at 1e10; out-of-band cells only
// feed out-of-band cells). softmin = m - poly_log2(1 + 2^(m-mid) + 2^(m-Mx)).
// ---------------------------------------------------------------------------
__global__ void __launch_bounds__(128) fused_dp_kernel(const float* __restrict__ X,
                                                       const float* __restrict__ Z)
{
    __shared__ float zsm[512 * 18];    // permuted Z rows: 16 data + z2*log2e + pad
    __shared__ float rings[5][32];     // warp w reads rings[w], writes rings[w+1]

    const int n    = blockIdx.x;
    const int tid  = threadIdx.x;
    const int w    = tid >> 5;
    const int lane = tid & 31;
    const int row0 = 4 * tid;

    // ---- stage Z into permuted smem (+ z2*log2e at offset 16) ----
    for (int r = tid; r < 512; r += 128) {
        const float* zg = Z + r * 16;
        float vals[16]; float s2 = 0.f;
        #pragma unroll
        for (int k = 0; k < 16; k++) { float v = zg[k]; vals[k] = v; s2 = fmaf(v, v, s2); }
        float* dst = zsm + ZSLOT(r) * 18;
        #pragma unroll
        for (int k = 0; k < 16; k++) dst[k] = vals[k];
        dst[16] = s2 * LOG2E;
    }
    for (int i = tid; i < 5 * 32; i += 128) (&rings[0][0])[i] = BIGL;

    // ---- stage X rows 4t..4t+3, pre-scaled by -2*log2e; x2L = x2*log2e ----
    ull xp[4][8]; float x2L[4];
    {
        const ull* Xp = (const ull*)(X + ((size_t)n * TLEN + row0) * DDIM);
        #pragma unroll
        for (int c = 0; c < 4; c++) {
            float s2 = 0.f;
            #pragma unroll
            for (int k = 0; k < 8; k++) {
                ull p = Xp[c * 8 + k];
                float lo, hi; UNPK(lo, hi, p);
                s2 = fmaf(lo, lo, fmaf(hi, hi, s2));
                lo *= -2.0f * LOG2E; hi *= -2.0f * LOG2E;
                PK(xp[c][k], lo, hi);
            }
            x2L[c] = s2 * LOG2E;
        }
    }

    float rc0 = BIGL, rc1 = BIGL, rc2 = BIGL, rc3 = BIGL;
    float rd0 = BIGL, rd1 = BIGL, rd2 = BIGL, rd3 = BIGL;
    if (tid == 0) rd0 = 0.0f;          // corner R[0][0]
    float resv = BIGL;

    float* ringr = &rings[w][0];       // warp 0 reads a never-written BIGL row
    float* ringw = &rings[w + 1][0];

    __syncthreads();                   // zsm + rings visible

    ull   zr[4][8];                    // 4-row Z cache; slot(z) = (z+row0)&3
    float z2c[4];                      // cached z2*log2e per slot
    float dD[2][4];                    // D ping-pong: dD[J&1][cell]

#define ZLOAD(SLOT, JUC)                                                       \
    {                                                                          \
        int jc = (JUC); jc = jc < 0 ? 0 : (jc > 511 ? 511 : jc);               \
        const ull* zp = (const ull*)(zsm + ZSLOT(jc) * 18);                    \
        zr[SLOT][0] = zp[0]; zr[SLOT][1] = zp[1];                              \
        zr[SLOT][2] = zp[2]; zr[SLOT][3] = zp[3];                              \
        zr[SLOT][4] = zp[4]; zr[SLOT][5] = zp[5];                              \
        zr[SLOT][6] = zp[6]; zr[SLOT][7] = zp[7];                              \
        z2c[SLOT] = ((const float*)zp)[16];                                    \
    }

// D = x2L + z2 - 2*log2e*dot  (x pre-scaled; zero addressing in hot path)
#define DCOMP(DST, C, SLOT)                                                    \
    {                                                                          \
        ull a0 = mul2(xp[C][0], zr[SLOT][0]);                                  \
        ull a1 = mul2(xp[C][1], zr[SLOT][1]);                                  \
        a0 = fma2(xp[C][2], zr[SLOT][2], a0);                                  \
        a1 = fma2(xp[C][3], zr[SLOT][3], a1);                                  \
        a0 = fma2(xp[C][4], zr[SLOT][4], a0);                                  \
        a1 = fma2(xp[C][5], zr[SLOT][5], a1);                                  \
        a0 = fma2(xp[C][6], zr[SLOT][6], a0);                                  \
        a1 = fma2(xp[C][7], zr[SLOT][7], a1);                                  \
        a0 = add2(a0, a1);                                                     \
        float lo, hi; UNPK(lo, hi, a0);                                        \
        (DST) = (lo + hi) + (x2L[C] + z2c[SLOT]);                              \
    }

// softmin cell: 2 ex2 (MUFU) + degree-6 Horner on the fma pipe (no lg2).
#define SOFTMIN_CELL(A, B, C, DVAL, RDOUT, RCOUT)                              \
    {                                                                          \
        float m  = fminf(fminf(A, B), C);                                      \
        float Mx = fmaxf(fmaxf(A, B), C);                                      \
        float mid = (((A) + (B)) + (C)) - m - Mx;                              \
        float e1 = ex2f(m - mid);                                              \
        float e2 = ex2f(m - Mx);                                               \
        float tt = (e1 + e2) - 1.0f;                                           \
        float pl = fmaf(PB6, tt, PB5);                                         \
        pl = fmaf(pl, tt, PB4);                                                \
        pl = fmaf(pl, tt, PB3);                                                \
        pl = fmaf(pl, tt, PB2);                                                \
        pl = fmaf(pl, tt, PB1);                                                \
        pl = fmaf(pl, tt, PB0);                                                \
        RDOUT = (A); RCOUT = ((DVAL) + m) - pl;                                \
    }

    // ---- prologue: prime Z cache + dD[0] for this warp's first diag ----
    const int kstart = -8 * w;
    ZLOAD(1, kstart - 3 - row0)
    ZLOAD(2, kstart - 2 - row0)
    ZLOAD(3, kstart - 1 - row0)
    ZLOAD(0, kstart + 0 - row0)
    DCOMP(dD[0][0], 0, 0)
    DCOMP(dD[0][1], 1, 3)
    DCOMP(dD[0][2], 2, 2)
    DCOMP(dD[0][3], 3, 1)
    ZLOAD(1, kstart + 1 - row0)        // cache = rows kstart-row0-2 .. +1

#define DP_STEP(J)                                                             \
    {                                                                          \
        const int cur = kwb + (J);                                             \
        const float bval = ringr[(cur - 1) & 31];                              \
        float upsh = __shfl_up_sync(0xffffffffu, rc3, 1);                      \
        const float u0 = (lane == 0) ? bval : upsh;                            \
        const float u1 = rc0, u2 = rc1, u3 = rc2;                              \
        SOFTMIN_CELL(u0, rc0, rd0, dD[(J) & 1][0], rd0, rc0)                   \
        SOFTMIN_CELL(u1, rc1, rd1, dD[(J) & 1][1], rd1, rc1)                   \
        SOFTMIN_CELL(u2, rc2, rd2, dD[(J) & 1][2], rd2, rc2)                   \
        SOFTMIN_CELL(u3, rc3, rd3, dD[(J) & 1][3], rd3, rc3)                   \
        if (cur == NDIAG - 1) resv = rc3;          /* row 511 result snapshot */ \
        if (lane == 31) ringw[cur & 31] = rc3;                                 \
        /* fused: D for diag cur+1 (cell3 reads slot (J-2)&3 BEFORE ZLOAD) */  \
        DCOMP(dD[((J) + 1) & 1][0], 0, ((J) + 1) & 3)                          \
        DCOMP(dD[((J) + 1) & 1][1], 1, ((J) + 0) & 3)                          \
        DCOMP(dD[((J) + 1) & 1][2], 2, ((J) - 1) & 3)                          \
        DCOMP(dD[((J) + 1) & 1][3], 3, ((J) - 2) & 3)                          \
        ZLOAD(((J) + 2) & 3, cur + 2 - row0)                                   \
    }

    #pragma unroll 1
    for (int p = 0; p < NPHASE; ++p) {
        const int kwb = 8 * p - 8 * w;
        DP_STEP(0) DP_STEP(1) DP_STEP(2) DP_STEP(3)
        DP_STEP(4) DP_STEP(5) DP_STEP(6) DP_STEP(7)
        __syncthreads();
    }
#undef DP_STEP
#undef SOFTMIN_CELL
#undef DCOMP
#undef ZLOAD

    if (tid == 127) g_res[n] = resv * LN2;     // row 511 at diag 1022: R[T,T]
}

// ---------------------------------------------------------------------------
// Deterministic weighted reduction.
// ---------------------------------------------------------------------------
__global__ void reduce_kernel(const float* __restrict__ wts, float* __restrict__ out)
{
    __shared__ float s[64];
    const int tid = threadIdx.x;
    s[tid] = g_res[tid] * wts[tid];
    __syncthreads();
    #pragma unroll
    for (int off = 32; off > 0; off >>= 1) {
        if (tid < off) s[tid] += s[tid + off];
        __syncthreads();
    }
    if (tid == 0) out[0] = s[0];
}

// ---------------------------------------------------------------------------
extern "C" void kernel_launch(void* const* d_in, const int* in_sizes, int n_in,
                              void* d_out, int out_size)
{
    const float* X = nullptr; const float* wts = nullptr; const float* Z = nullptr;
    for (int i = 0; i < n_in; i++) {
        if      (in_sizes[i] == NSAMP)        wts = (const float*)d_in[i];
        else if (in_sizes[i] == TLEN * DDIM)  Z   = (const float*)d_in[i];
        else                                  X   = (const float*)d_in[i];
    }
    float* out = (float*)d_out;

    fused_dp_kernel<<<NSAMP, 128>>>(X, Z);
    reduce_kernel<<<1, 64>>>(wts, out);
}